// round 15
// baseline (speedup 1.0000x reference)
#include <cuda_runtime.h>
#include <math.h>

#define BB 2
#define SS_ 2048
#define DD 512
#define HH 8
#define DFF 2048
#define NTOK (BB*SS_)          // 4096
#define EPS 1e-5f

typedef unsigned long long ull;
typedef unsigned int u32;

// tf32 mma: HW reads high 19 bits; pass raw fp32 bits (CUTLASS-style).
__device__ __forceinline__ u32 fu(float x) { return __float_as_uint(x); }
__device__ __forceinline__ void mma8(float4& d, u32 a0, u32 a1, u32 a2, u32 a3,
                                     u32 b0, u32 b1) {
    asm("mma.sync.aligned.m16n8k8.row.col.f32.tf32.tf32.f32 "
        "{%0,%1,%2,%3},{%4,%5,%6,%7},{%8,%9},{%0,%1,%2,%3};"
        : "+f"(d.x), "+f"(d.y), "+f"(d.z), "+f"(d.w)
        : "r"(a0), "r"(a1), "r"(a2), "r"(a3), "r"(b0), "r"(b1));
}
__device__ __forceinline__ u32 s2u(const void* p) {
    return (u32)__cvta_generic_to_shared(p);
}
__device__ __forceinline__ void cpa(u32 dst, const void* src) {
    asm volatile("cp.async.cg.shared.global [%0], [%1], 16;"
                 :: "r"(dst), "l"(src));
}
#define CP_COMMIT() asm volatile("cp.async.commit_group;" ::: "memory")
#define CP_WAIT2()  asm volatile("cp.async.wait_group 2;" ::: "memory")
#define CP_WAIT0()  asm volatile("cp.async.wait_group 0;" ::: "memory")

// ------------------------------ scratch ------------------------------------
__device__ float g_qb[BB*HH*SS_*64];
__device__ float g_kb[BB*HH*SS_*64];
__device__ float g_vb[BB*HH*SS_*64];
__device__ float g_ctx[NTOK*DD];
__device__ float g_t1[NTOK*DD];
__device__ float g_ao[NTOK*DD];
__device__ float g_h[NTOK*DFF];
__device__ float g_t2[NTOK*DD];
__device__ float g_attn[(size_t)BB*HH*SS_*SS_];   // fallback if attn not in d_out
__device__ u32   g_maskbits[BB*SS_*64];           // 1 MB packed mask bits
__device__ int   g_maskmode;               // 0 = int32 mask, 1 = uint8 mask

__global__ void detect_mask_kernel(const unsigned int* __restrict__ m)
{
    if (threadIdx.x == 0 && blockIdx.x == 0) {
        int mode = 0;
        for (int i = 0; i < 4096; i++) {
            if (m[i] > 1u) { mode = 1; break; }
        }
        g_maskmode = mode;
    }
}

// pack mask (int32 or uint8) into bits: word i covers elements [32i, 32i+32)
__global__ __launch_bounds__(256) void pack_mask_kernel(const void* __restrict__ mask)
{
    int i = blockIdx.x * 256 + threadIdx.x;        // 0 .. BB*SS_*64-1
    int mm = g_maskmode;
    u32 b = 0;
    if (mm == 0) {
        const int4* p = (const int4*)mask + (size_t)i * 8;
#pragma unroll
        for (int j = 0; j < 8; j++) {
            int4 m = p[j];
            b |= (m.x ? 1u : 0u) << (j * 4 + 0);
            b |= (m.y ? 1u : 0u) << (j * 4 + 1);
            b |= (m.z ? 1u : 0u) << (j * 4 + 2);
            b |= (m.w ? 1u : 0u) << (j * 4 + 3);
        }
    } else {
        const uchar4* p = (const uchar4*)mask + (size_t)i * 8;
#pragma unroll
        for (int j = 0; j < 8; j++) {
            uchar4 m = p[j];
            b |= (m.x ? 1u : 0u) << (j * 4 + 0);
            b |= (m.y ? 1u : 0u) << (j * 4 + 1);
            b |= (m.z ? 1u : 0u) << (j * 4 + 2);
            b |= (m.w ? 1u : 0u) << (j * 4 + 3);
        }
    }
    g_maskbits[i] = b;
}

// ------------------------------ tf32 GEMM (4-stage cp.async, templated N) --
#define AST 20
#define A_STG (128*AST)

template<int NT>
__device__ __forceinline__ void gemm_issue(
    u32 sb, int c, int NCH, const float* A, const float* W,
    int K, int N, int rowBase, int colBase, int tid)
{
    constexpr int WSTn = NT + 8;
    constexpr int STG = A_STG + 16 * WSTn;
    if (c < NCH) {
        int k0 = c * 16;
        u32 as = sb + (u32)((c & 3) * STG) * 4u;
        u32 ws = as + A_STG * 4u;
        int f0 = tid, f1 = tid + 256;
        cpa(as + (u32)((f0 >> 2) * AST + (f0 & 3) * 4) * 4u,
            A + (size_t)(rowBase + (f0 >> 2)) * K + k0 + (f0 & 3) * 4);
        cpa(as + (u32)((f1 >> 2) * AST + (f1 & 3) * 4) * 4u,
            A + (size_t)(rowBase + (f1 >> 2)) * K + k0 + (f1 & 3) * 4);
#pragma unroll
        for (int u = 0; u < NT / 64; u++) {
            int f = tid + u * 256;
            int r = f / (NT / 4), c4 = (f % (NT / 4)) * 4;
            cpa(ws + (u32)(r * WSTn + c4) * 4u,
                W + (size_t)(k0 + r) * N + colBase + c4);
        }
    }
    CP_COMMIT();
}

template<int NT>
__device__ __forceinline__ void gemm_tc_body(
    const float* __restrict__ A, const float* __restrict__ W,
    const float* __restrict__ bias, const float* __restrict__ resid,
    float* __restrict__ C, int N, int K, int doRelu, int headStore,
    int rowBase, int colBase, float* smem)
{
    constexpr int WSTn = NT + 8;
    constexpr int STG = A_STG + 16 * WSTn;
    constexpr int NF = NT / 16;
    int tid = threadIdx.x;
    int w = tid >> 5, t = tid & 31;
    int wr = w >> 1, wc = w & 1;
    int tq = t >> 2, tr = t & 3;
    u32 sb = s2u(smem);
    int NCH = K >> 4;

    float4 acc[2][NF];
#pragma unroll
    for (int f = 0; f < 2; f++)
#pragma unroll
        for (int nf = 0; nf < NF; nf++) acc[f][nf] = make_float4(0.f,0.f,0.f,0.f);

    gemm_issue<NT>(sb, 0, NCH, A, W, K, N, rowBase, colBase, tid);
    gemm_issue<NT>(sb, 1, NCH, A, W, K, N, rowBase, colBase, tid);
    gemm_issue<NT>(sb, 2, NCH, A, W, K, N, rowBase, colBase, tid);

    for (int i = 0; i < NCH; i++) {
        CP_WAIT2();
        __syncthreads();
        gemm_issue<NT>(sb, i + 3, NCH, A, W, K, N, rowBase, colBase, tid);

        const float* As = smem + (i & 3) * STG;
        const float* Ws = As + A_STG;
#pragma unroll
        for (int kh = 0; kh < 2; kh++) {
            u32 a0[2], a1[2], a2[2], a3[2];
#pragma unroll
            for (int f = 0; f < 2; f++) {
                int rb = wr * 32 + f * 16;
                a0[f] = fu(As[(rb + tq) * AST + kh * 8 + tr]);
                a1[f] = fu(As[(rb + tq + 8) * AST + kh * 8 + tr]);
                a2[f] = fu(As[(rb + tq) * AST + kh * 8 + tr + 4]);
                a3[f] = fu(As[(rb + tq + 8) * AST + kh * 8 + tr + 4]);
            }
#pragma unroll
            for (int nf = 0; nf < NF; nf++) {
                int n = wc * (NT / 2) + nf * 8 + tq;
                u32 b0 = fu(Ws[(kh * 8 + tr) * WSTn + n]);
                u32 b1 = fu(Ws[(kh * 8 + tr + 4) * WSTn + n]);
#pragma unroll
                for (int f = 0; f < 2; f++)
                    mma8(acc[f][nf], a0[f], a1[f], a2[f], a3[f], b0, b1);
            }
        }
    }

#pragma unroll
    for (int f = 0; f < 2; f++) {
        int row = rowBase + wr * 32 + f * 16 + tq;
#pragma unroll
        for (int nf = 0; nf < NF; nf++) {
            int col = colBase + wc * (NT / 2) + nf * 8 + tr * 2;
            float b0 = bias[col], b1 = bias[col + 1];
            float c00 = acc[f][nf].x + b0, c01 = acc[f][nf].y + b1;
            float c10 = acc[f][nf].z + b0, c11 = acc[f][nf].w + b1;
            if (resid) {
                float2 r0 = *(const float2*)(resid + (size_t)row * N + col);
                float2 r1 = *(const float2*)(resid + (size_t)(row + 8) * N + col);
                c00 += r0.x; c01 += r0.y; c10 += r1.x; c11 += r1.y;
            }
            if (doRelu) {
                c00 = fmaxf(c00, 0.f); c01 = fmaxf(c01, 0.f);
                c10 = fmaxf(c10, 0.f); c11 = fmaxf(c11, 0.f);
            }
            if (headStore) {
                int h_ = col >> 6, d_ = col & 63;
                int b0_ = row / SS_, s0_ = row % SS_;
                *(float2*)&C[(((size_t)(b0_ * HH + h_)) * SS_ + s0_) * 64 + d_] =
                    make_float2(c00, c01);
                int b1_ = (row + 8) / SS_, s1_ = (row + 8) % SS_;
                *(float2*)&C[(((size_t)(b1_ * HH + h_)) * SS_ + s1_) * 64 + d_] =
                    make_float2(c10, c11);
            } else {
                *(float2*)&C[(size_t)row * N + col] = make_float2(c00, c01);
                *(float2*)&C[(size_t)(row + 8) * N + col] = make_float2(c10, c11);
            }
        }
    }
}

#define GEMM128_SMEM_BYTES (4*(A_STG + 16*136)*4)   // 75776
#define GEMM64_SMEM_BYTES  (4*(A_STG + 16*72)*4)    // 59392

__global__ __launch_bounds__(256, 2) void sgemm128_kernel(
    const float* __restrict__ A, const float* __restrict__ W,
    const float* __restrict__ bias, const float* __restrict__ resid,
    float* __restrict__ C, int N, int K, int doRelu)
{
    extern __shared__ float smem[];
    gemm_tc_body<128>(A, W, bias, resid, C, N, K, doRelu, 0,
                      blockIdx.y * 128, blockIdx.x * 128, smem);
}

__global__ __launch_bounds__(256, 2) void sgemm64_kernel(
    const float* __restrict__ A, const float* __restrict__ W,
    const float* __restrict__ bias, const float* __restrict__ resid,
    float* __restrict__ C, int N, int K, int doRelu)
{
    extern __shared__ float smem[];
    gemm_tc_body<64>(A, W, bias, resid, C, N, K, doRelu, 0,
                     blockIdx.y * 128, blockIdx.x * 64, smem);
}

__global__ __launch_bounds__(256, 2) void qkv_kernel(
    const float* __restrict__ A,
    const float* __restrict__ Wq, const float* __restrict__ bq,
    const float* __restrict__ Wk, const float* __restrict__ bk,
    const float* __restrict__ Wv, const float* __restrict__ bv,
    float* __restrict__ q, float* __restrict__ k, float* __restrict__ v)
{
    extern __shared__ float smem[];
    int sel = blockIdx.x >> 2;
    const float* W = (sel == 0) ? Wq : (sel == 1) ? Wk : Wv;
    const float* bias = (sel == 0) ? bq : (sel == 1) ? bk : bv;
    float* C = (sel == 0) ? q : (sel == 1) ? k : v;
    gemm_tc_body<128>(A, W, bias, nullptr, C, DD, DD, 0, 1,
                      blockIdx.y * 128, (blockIdx.x & 3) * 128, smem);
}

// ------------------------------ qk: S = mask(Q K^T / 8) --------------------
// grid (16 key-tiles, 16 row-tiles, 16 bh), 256 thr = 8 warps (4x2).
#define QKT 68
#define QK_TILE (128*QKT)
#define QK_SMEM_BYTES (2*QK_TILE*4)

__global__ __launch_bounds__(256, 2) void qk_kernel(
    const float* __restrict__ q, const float* __restrict__ k,
    float* __restrict__ attn)
{
    extern __shared__ float smem[];
    float* Qs = smem;
    float* Ks = smem + QK_TILE;

    int tid = threadIdx.x;
    int w = tid >> 5, t = tid & 31;
    int wr = w >> 1, wc = w & 1;
    int tq = t >> 2, tr = t & 3;
    int bh = blockIdx.z, b_ = bh >> 3;
    int row0 = blockIdx.y * 128;
    int col0 = blockIdx.x * 128;

    const float* qptr = q + ((size_t)bh * SS_ + row0) * 64;
    const float* kptr = k + ((size_t)bh * SS_ + col0) * 64;
    const u32* mbits = g_maskbits + (size_t)b_ * SS_ * 64;
    u32 sb = s2u(smem);

#pragma unroll
    for (int i = 0; i < 8; i++) {
        int f = tid + i * 256;
        int r = f >> 4, c4 = (f & 15) * 4;
        cpa(sb + (u32)(r * QKT + c4) * 4u, qptr + (size_t)r * 64 + c4);
        cpa(sb + (u32)(QK_TILE + r * QKT + c4) * 4u, kptr + (size_t)r * 64 + c4);
    }
    CP_COMMIT();
    CP_WAIT0();
    __syncthreads();

    float4 acc[2][8];
#pragma unroll
    for (int f = 0; f < 2; f++)
#pragma unroll
        for (int nf = 0; nf < 8; nf++) acc[f][nf] = make_float4(0.f,0.f,0.f,0.f);

#pragma unroll
    for (int j = 0; j < 8; j++) {
        u32 a0[2], a1[2], a2[2], a3[2];
#pragma unroll
        for (int f = 0; f < 2; f++) {
            int rb = wr * 32 + f * 16;
            a0[f] = fu(Qs[(rb + tq) * QKT + j * 8 + tr]);
            a1[f] = fu(Qs[(rb + tq + 8) * QKT + j * 8 + tr]);
            a2[f] = fu(Qs[(rb + tq) * QKT + j * 8 + tr + 4]);
            a3[f] = fu(Qs[(rb + tq + 8) * QKT + j * 8 + tr + 4]);
        }
#pragma unroll
        for (int nf = 0; nf < 8; nf++) {
            int n = wc * 64 + nf * 8 + tq;
            u32 b0 = fu(Ks[n * QKT + j * 8 + tr]);
            u32 b1 = fu(Ks[n * QKT + j * 8 + tr + 4]);
#pragma unroll
            for (int f = 0; f < 2; f++)
                mma8(acc[f][nf], a0[f], a1[f], a2[f], a3[f], b0, b1);
        }
    }

#pragma unroll
    for (int f = 0; f < 2; f++) {
        int row = row0 + wr * 32 + f * 16 + tq;
#pragma unroll
        for (int nf = 0; nf < 8; nf++) {
            int col = col0 + wc * 64 + nf * 8 + tr * 2;
            float4 a = acc[f][nf];
            u32 w0 = mbits[(size_t)row * 64 + (col >> 5)];
            u32 w1 = mbits[(size_t)(row + 8) * 64 + (col >> 5)];
            int sh = col & 31;
            float2 s0, s1;
            s0.x = ((w0 >> sh) & 1u)       ? -1e9f : a.x * 0.125f;
            s0.y = ((w0 >> (sh + 1)) & 1u) ? -1e9f : a.y * 0.125f;
            s1.x = ((w1 >> sh) & 1u)       ? -1e9f : a.z * 0.125f;
            s1.y = ((w1 >> (sh + 1)) & 1u) ? -1e9f : a.w * 0.125f;
            *(float2*)&attn[((size_t)bh * SS_ + row) * SS_ + col] = s0;
            *(float2*)&attn[((size_t)bh * SS_ + row + 8) * SS_ + col] = s1;
        }
    }
}

// ------------------------------ softmax: normalize rows in place -----------
__global__ __launch_bounds__(256) void softmax_kernel(float* __restrict__ attn)
{
    int w = threadIdx.x >> 5, lane = threadIdx.x & 31;
    size_t row = (size_t)blockIdx.x * 8 + w;
    float4* p = (float4*)(attn + row * SS_);

    float4 v[16];
#pragma unroll
    for (int i = 0; i < 16; i++) v[i] = p[lane + i * 32];

    float mx = -1e30f;
#pragma unroll
    for (int i = 0; i < 16; i++)
        mx = fmaxf(mx, fmaxf(fmaxf(v[i].x, v[i].y), fmaxf(v[i].z, v[i].w)));
#pragma unroll
    for (int o = 16; o; o >>= 1)
        mx = fmaxf(mx, __shfl_xor_sync(0xffffffffu, mx, o));

    float sm = 0.f;
#pragma unroll
    for (int i = 0; i < 16; i++) {
        v[i].x = __expf(v[i].x - mx); v[i].y = __expf(v[i].y - mx);
        v[i].z = __expf(v[i].z - mx); v[i].w = __expf(v[i].w - mx);
        sm += v[i].x + v[i].y + v[i].z + v[i].w;
    }
#pragma unroll
    for (int o = 16; o; o >>= 1)
        sm += __shfl_xor_sync(0xffffffffu, sm, o);
    float inv = 1.f / sm;

#pragma unroll
    for (int i = 0; i < 16; i++) {
        v[i].x *= inv; v[i].y *= inv; v[i].z *= inv; v[i].w *= inv;
        p[lane + i * 32] = v[i];
    }
}

// ------------------------------ pv: ctx = attn @ V (4-stage cp.async) ------
#define PAST 20
#define PA_STG (128*PAST)
#define PVST 72
#define PV_STG (16*PVST)
#define PSTG_WORDS (PA_STG + PV_STG)
#define PV_SMEM_BYTES (4*PSTG_WORDS*4)

__device__ __forceinline__ void pv_issue(
    u32 sb, int c, const float* P, const float* V, int tid)
{
    if (c < 128) {
        int k0 = c * 16;
        u32 as = sb + (u32)((c & 3) * PSTG_WORDS) * 4u;
        u32 vs = as + PA_STG * 4u;
        int f0 = tid, f1 = tid + 256;
        cpa(as + (u32)((f0 >> 2) * PAST + (f0 & 3) * 4) * 4u,
            P + (size_t)(f0 >> 2) * SS_ + k0 + (f0 & 3) * 4);
        cpa(as + (u32)((f1 >> 2) * PAST + (f1 & 3) * 4) * 4u,
            P + (size_t)(f1 >> 2) * SS_ + k0 + (f1 & 3) * 4);
        cpa(vs + (u32)((tid >> 4) * PVST + (tid & 15) * 4) * 4u,
            V + (size_t)(k0 + (tid >> 4)) * 64 + (tid & 15) * 4);
    }
    CP_COMMIT();
}

__global__ __launch_bounds__(256, 2) void pv_kernel(
    const float* __restrict__ attn, const float* __restrict__ v,
    float* __restrict__ ctx)
{
    extern __shared__ float smem[];
    int tid = threadIdx.x;
    int w = tid >> 5, t = tid & 31;
    int tq = t >> 2, tr = t & 3;
    int bh = blockIdx.y, b_ = bh >> 3, h_ = bh & 7;
    int row0 = blockIdx.x * 128;
    u32 sb = s2u(smem);

    const float* P = attn + (size_t)bh * SS_ * SS_ + (size_t)row0 * SS_;
    const float* V = v + (size_t)bh * SS_ * 64;

    float4 acc[8];
#pragma unroll
    for (int nf = 0; nf < 8; nf++) acc[nf] = make_float4(0.f,0.f,0.f,0.f);

    pv_issue(sb, 0, P, V, tid);
    pv_issue(sb, 1, P, V, tid);
    pv_issue(sb, 2, P, V, tid);

    for (int i = 0; i < 128; i++) {
        CP_WAIT2();
        __syncthreads();
        pv_issue(sb, i + 3, P, V, tid);

        const float* As = smem + (i & 3) * PSTG_WORDS;
        const float* Vs = As + PA_STG;
        int rb = w * 16;
#pragma unroll
        for (int kh = 0; kh < 2; kh++) {
            u32 a0 = fu(As[(rb + tq) * PAST + kh * 8 + tr]);
            u32 a1 = fu(As[(rb + tq + 8) * PAST + kh * 8 + tr]);
            u32 a2 = fu(As[(rb + tq) * PAST + kh * 8 + tr + 4]);
            u32 a3 = fu(As[(rb + tq + 8) * PAST + kh * 8 + tr + 4]);
#pragma unroll
            for (int nf = 0; nf < 8; nf++) {
                int n = nf * 8 + tq;
                u32 b0 = fu(Vs[(kh * 8 + tr) * PVST + n]);
                u32 b1 = fu(Vs[(kh * 8 + tr + 4) * PVST + n]);
                mma8(acc[nf], a0, a1, a2, a3, b0, b1);
            }
        }
    }

    int r0 = row0 + w * 16 + tq;
#pragma unroll
    for (int nf = 0; nf < 8; nf++) {
        int col = h_ * 64 + nf * 8 + tr * 2;
        *(float2*)&ctx[((size_t)(b_ * SS_ + r0)) * DD + col] =
            make_float2(acc[nf].x, acc[nf].y);
        *(float2*)&ctx[((size_t)(b_ * SS_ + r0 + 8)) * DD + col] =
            make_float2(acc[nf].z, acc[nf].w);
    }
}

// ------------------------------ layernorm ----------------------------------
__global__ __launch_bounds__(128) void ln_kernel(
    const float* __restrict__ x, const float* __restrict__ gamma,
    const float* __restrict__ beta, float* __restrict__ out)
{
    int row = blockIdx.x;
    int tid = threadIdx.x;
    __shared__ float red[4];
    float4 v = ((const float4*)(x + (size_t)row * DD))[tid];
    float s = v.x + v.y + v.z + v.w;
#pragma unroll
    for (int o = 16; o; o >>= 1) s += __shfl_xor_sync(0xffffffffu, s, o);
    if ((tid & 31) == 0) red[tid >> 5] = s;
    __syncthreads();
    float mu = (red[0] + red[1] + red[2] + red[3]) * (1.f / DD);
    float dx = v.x - mu, dy = v.y - mu, dz = v.z - mu, dw = v.w - mu;
    float s2 = dx * dx + dy * dy + dz * dz + dw * dw;
#pragma unroll
    for (int o = 16; o; o >>= 1) s2 += __shfl_xor_sync(0xffffffffu, s2, o);
    __syncthreads();
    if ((tid & 31) == 0) red[tid >> 5] = s2;
    __syncthreads();
    float var = (red[0] + red[1] + red[2] + red[3]) * (1.f / DD);
    float inv = rsqrtf(var + EPS);
    float4 gg = ((const float4*)gamma)[tid];
    float4 bb = ((const float4*)beta)[tid];
    float4 o;
    o.x = dx * inv * gg.x + bb.x;
    o.y = dy * inv * gg.y + bb.y;
    o.z = dz * inv * gg.z + bb.z;
    o.w = dw * inv * gg.w + bb.w;
    *(float4*)(out + (size_t)row * DD + tid * 4) = o;
}

// ------------------------------ launch -------------------------------------
extern "C" void kernel_launch(void* const* d_in, const int* in_sizes, int n_in,
                              void* d_out, int out_size)
{
    const float* x   = (const float*)d_in[0];
    const void*  mask = d_in[1];
    const float* Wq  = (const float*)d_in[2];
    const float* bq  = (const float*)d_in[3];
    const float* Wk  = (const float*)d_in[4];
    const float* bk  = (const float*)d_in[5];
    const float* Wv  = (const float*)d_in[6];
    const float* bv  = (const float*)d_in[7];
    const float* Wo  = (const float*)d_in[8];
    const float* bo  = (const float*)d_in[9];
    const float* ln1g = (const float*)d_in[10];
    const float* ln1b = (const float*)d_in[11];
    const float* W1  = (const float*)d_in[12];
    const float* b1  = (const float*)d_in[13];
    const float* W2  = (const float*)d_in[14];
    const float* b2  = (const float*)d_in[15];
    const float* ln2g = (const float*)d_in[16];
    const float* ln2b = (const float*)d_in[17];

    float* out = (float*)d_out;
    const long OUT_ELEMS = (long)BB * SS_ * DD;
    const long ATTN_ELEMS = (long)BB * HH * SS_ * SS_;

    float *qp, *kp, *vp, *ctxp, *t1p, *aop, *hp, *t2p, *attnScratch;
    cudaGetSymbolAddress((void**)&qp, g_qb);
    cudaGetSymbolAddress((void**)&kp, g_kb);
    cudaGetSymbolAddress((void**)&vp, g_vb);
    cudaGetSymbolAddress((void**)&ctxp, g_ctx);
    cudaGetSymbolAddress((void**)&t1p, g_t1);
    cudaGetSymbolAddress((void**)&aop, g_ao);
    cudaGetSymbolAddress((void**)&hp, g_h);
    cudaGetSymbolAddress((void**)&t2p, g_t2);
    cudaGetSymbolAddress((void**)&attnScratch, g_attn);

    float* attn_ptr = ((long)out_size >= OUT_ELEMS + ATTN_ELEMS)
                        ? (out + OUT_ELEMS) : attnScratch;

    cudaFuncSetAttribute(sgemm128_kernel,
                         cudaFuncAttributeMaxDynamicSharedMemorySize,
                         GEMM128_SMEM_BYTES);
    cudaFuncSetAttribute(sgemm64_kernel,
                         cudaFuncAttributeMaxDynamicSharedMemorySize,
                         GEMM64_SMEM_BYTES);
    cudaFuncSetAttribute(qkv_kernel,
                         cudaFuncAttributeMaxDynamicSharedMemorySize,
                         GEMM128_SMEM_BYTES);
    cudaFuncSetAttribute(qk_kernel,
                         cudaFuncAttributeMaxDynamicSharedMemorySize,
                         QK_SMEM_BYTES);
    cudaFuncSetAttribute(pv_kernel,
                         cudaFuncAttributeMaxDynamicSharedMemorySize,
                         PV_SMEM_BYTES);

    dim3 blk(256);
    detect_mask_kernel<<<1, 32>>>((const unsigned int*)mask);
    pack_mask_kernel<<<BB * SS_ * 64 / 256, blk>>>(mask);
    qkv_kernel<<<dim3(12, 32), blk, GEMM128_SMEM_BYTES>>>(
        x, Wq, bq, Wk, bk, Wv, bv, qp, kp, vp);
    qk_kernel<<<dim3(16, 16, BB * HH), blk, QK_SMEM_BYTES>>>(
        qp, kp, attn_ptr);
    softmax_kernel<<<BB * HH * SS_ / 8, blk>>>(attn_ptr);
    pv_kernel<<<dim3(16, BB * HH), blk, PV_SMEM_BYTES>>>(attn_ptr, vp, ctxp);
    sgemm64_kernel<<<dim3(8, 32), blk, GEMM64_SMEM_BYTES>>>(
        ctxp, Wo, bo, x, t1p, DD, DD, 0);
    ln_kernel<<<NTOK, 128>>>(t1p, ln1g, ln1b, aop);
    sgemm128_kernel<<<dim3(16, 32), blk, GEMM128_SMEM_BYTES>>>(
        aop, W1, b1, nullptr, hp, DFF, DD, 1);
    sgemm64_kernel<<<dim3(8, 32), blk, GEMM64_SMEM_BYTES>>>(
        hp, W2, b2, aop, t2p, DD, DFF, 0);
    ln_kernel<<<NTOK, 128>>>(t2p, ln2g, ln2b, out);
}

// round 16
// speedup vs baseline: 1.0057x; 1.0057x over previous
#include <cuda_runtime.h>
#include <math.h>

#define BB 2
#define SS_ 2048
#define DD 512
#define HH 8
#define DFF 2048
#define NTOK (BB*SS_)          // 4096
#define EPS 1e-5f

typedef unsigned long long ull;
typedef unsigned int u32;

// tf32 mma: HW reads high 19 bits; pass raw fp32 bits (CUTLASS-style).
__device__ __forceinline__ u32 fu(float x) { return __float_as_uint(x); }
__device__ __forceinline__ void mma8(float4& d, u32 a0, u32 a1, u32 a2, u32 a3,
                                     u32 b0, u32 b1) {
    asm("mma.sync.aligned.m16n8k8.row.col.f32.tf32.tf32.f32 "
        "{%0,%1,%2,%3},{%4,%5,%6,%7},{%8,%9},{%0,%1,%2,%3};"
        : "+f"(d.x), "+f"(d.y), "+f"(d.z), "+f"(d.w)
        : "r"(a0), "r"(a1), "r"(a2), "r"(a3), "r"(b0), "r"(b1));
}
__device__ __forceinline__ void ldsm4(u32& r0, u32& r1, u32& r2, u32& r3, u32 a) {
    asm volatile("ldmatrix.sync.aligned.m8n8.x4.shared.b16 {%0,%1,%2,%3}, [%4];"
                 : "=r"(r0), "=r"(r1), "=r"(r2), "=r"(r3) : "r"(a));
}
__device__ __forceinline__ u32 s2u(const void* p) {
    return (u32)__cvta_generic_to_shared(p);
}
__device__ __forceinline__ void cpa(u32 dst, const void* src) {
    asm volatile("cp.async.cg.shared.global [%0], [%1], 16;"
                 :: "r"(dst), "l"(src));
}
#define CP_COMMIT() asm volatile("cp.async.commit_group;" ::: "memory")
#define CP_WAIT2()  asm volatile("cp.async.wait_group 2;" ::: "memory")
#define CP_WAIT0()  asm volatile("cp.async.wait_group 0;" ::: "memory")

// ------------------------------ scratch ------------------------------------
__device__ float g_qb[BB*HH*SS_*64];
__device__ float g_kb[BB*HH*SS_*64];
__device__ float g_vb[BB*HH*SS_*64];
__device__ float g_ctx[NTOK*DD];
__device__ float g_t1[NTOK*DD];
__device__ float g_ao[NTOK*DD];
__device__ float g_h[NTOK*DFF];
__device__ float g_t2[NTOK*DD];
__device__ float g_attn[(size_t)BB*HH*SS_*SS_];   // fallback if attn not in d_out
__device__ u32   g_maskbits[BB*SS_*64];           // 1 MB packed mask bits
__device__ int   g_maskmode;               // 0 = int32 mask, 1 = uint8 mask

__global__ void detect_mask_kernel(const unsigned int* __restrict__ m)
{
    if (threadIdx.x == 0 && blockIdx.x == 0) {
        int mode = 0;
        for (int i = 0; i < 4096; i++) {
            if (m[i] > 1u) { mode = 1; break; }
        }
        g_maskmode = mode;
    }
}

// pack mask (int32 or uint8) into bits: word i covers elements [32i, 32i+32)
__global__ __launch_bounds__(256) void pack_mask_kernel(const void* __restrict__ mask)
{
    int i = blockIdx.x * 256 + threadIdx.x;        // 0 .. BB*SS_*64-1
    int mm = g_maskmode;
    u32 b = 0;
    if (mm == 0) {
        const int4* p = (const int4*)mask + (size_t)i * 8;
#pragma unroll
        for (int j = 0; j < 8; j++) {
            int4 m = p[j];
            b |= (m.x ? 1u : 0u) << (j * 4 + 0);
            b |= (m.y ? 1u : 0u) << (j * 4 + 1);
            b |= (m.z ? 1u : 0u) << (j * 4 + 2);
            b |= (m.w ? 1u : 0u) << (j * 4 + 3);
        }
    } else {
        const uchar4* p = (const uchar4*)mask + (size_t)i * 8;
#pragma unroll
        for (int j = 0; j < 8; j++) {
            uchar4 m = p[j];
            b |= (m.x ? 1u : 0u) << (j * 4 + 0);
            b |= (m.y ? 1u : 0u) << (j * 4 + 1);
            b |= (m.z ? 1u : 0u) << (j * 4 + 2);
            b |= (m.w ? 1u : 0u) << (j * 4 + 3);
        }
    }
    g_maskbits[i] = b;
}

// ------------------------------ tf32 GEMM (4-stage cp.async, N=128) --------
#define AST 20
#define WST 136
#define A_STG (128*AST)
#define W_STG (16*WST)
#define STG_WORDS (A_STG + W_STG)
#define GEMM_SMEM_BYTES (4*STG_WORDS*4)

__device__ __forceinline__ void gemm_issue(
    u32 sb, int c, int NCH, const float* A, const float* W,
    int K, int N, int rowBase, int colBase, int tid)
{
    if (c < NCH) {
        int k0 = c * 16;
        u32 as = sb + (u32)((c & 3) * STG_WORDS) * 4u;
        u32 ws = as + A_STG * 4u;
        int f0 = tid, f1 = tid + 256;
        cpa(as + (u32)((f0 >> 2) * AST + (f0 & 3) * 4) * 4u,
            A + (size_t)(rowBase + (f0 >> 2)) * K + k0 + (f0 & 3) * 4);
        cpa(as + (u32)((f1 >> 2) * AST + (f1 & 3) * 4) * 4u,
            A + (size_t)(rowBase + (f1 >> 2)) * K + k0 + (f1 & 3) * 4);
        cpa(ws + (u32)((f0 >> 5) * WST + (f0 & 31) * 4) * 4u,
            W + (size_t)(k0 + (f0 >> 5)) * N + colBase + (f0 & 31) * 4);
        cpa(ws + (u32)((f1 >> 5) * WST + (f1 & 31) * 4) * 4u,
            W + (size_t)(k0 + (f1 >> 5)) * N + colBase + (f1 & 31) * 4);
    }
    CP_COMMIT();
}

__device__ __forceinline__ void gemm_tc_body(
    const float* __restrict__ A, const float* __restrict__ W,
    const float* __restrict__ bias, const float* __restrict__ resid,
    float* __restrict__ C, int N, int K, int doRelu, int headStore,
    int rowBase, int colBase, float* smem)
{
    int tid = threadIdx.x;
    int w = tid >> 5, t = tid & 31;
    int wr = w >> 1, wc = w & 1;
    int tq = t >> 2, tr = t & 3;
    u32 sb = s2u(smem);
    int NCH = K >> 4;

    float4 acc[2][8];
#pragma unroll
    for (int f = 0; f < 2; f++)
#pragma unroll
        for (int nf = 0; nf < 8; nf++) acc[f][nf] = make_float4(0.f,0.f,0.f,0.f);

    gemm_issue(sb, 0, NCH, A, W, K, N, rowBase, colBase, tid);
    gemm_issue(sb, 1, NCH, A, W, K, N, rowBase, colBase, tid);
    gemm_issue(sb, 2, NCH, A, W, K, N, rowBase, colBase, tid);

    for (int i = 0; i < NCH; i++) {
        CP_WAIT2();
        __syncthreads();
        gemm_issue(sb, i + 3, NCH, A, W, K, N, rowBase, colBase, tid);

        const float* As = smem + (i & 3) * STG_WORDS;
        const float* Ws = As + A_STG;
#pragma unroll
        for (int kh = 0; kh < 2; kh++) {
            u32 a0[2], a1[2], a2[2], a3[2];
#pragma unroll
            for (int f = 0; f < 2; f++) {
                int rb = wr * 32 + f * 16;
                a0[f] = fu(As[(rb + tq) * AST + kh * 8 + tr]);
                a1[f] = fu(As[(rb + tq + 8) * AST + kh * 8 + tr]);
                a2[f] = fu(As[(rb + tq) * AST + kh * 8 + tr + 4]);
                a3[f] = fu(As[(rb + tq + 8) * AST + kh * 8 + tr + 4]);
            }
#pragma unroll
            for (int nf = 0; nf < 8; nf++) {
                int n = wc * 64 + nf * 8 + tq;
                u32 b0 = fu(Ws[(kh * 8 + tr) * WST + n]);
                u32 b1 = fu(Ws[(kh * 8 + tr + 4) * WST + n]);
#pragma unroll
                for (int f = 0; f < 2; f++)
                    mma8(acc[f][nf], a0[f], a1[f], a2[f], a3[f], b0, b1);
            }
        }
    }

#pragma unroll
    for (int f = 0; f < 2; f++) {
        int row = rowBase + wr * 32 + f * 16 + tq;
#pragma unroll
        for (int nf = 0; nf < 8; nf++) {
            int col = colBase + wc * 64 + nf * 8 + tr * 2;
            float b0 = bias[col], b1 = bias[col + 1];
            float c00 = acc[f][nf].x + b0, c01 = acc[f][nf].y + b1;
            float c10 = acc[f][nf].z + b0, c11 = acc[f][nf].w + b1;
            if (resid) {
                float2 r0 = *(const float2*)(resid + (size_t)row * N + col);
                float2 r1 = *(const float2*)(resid + (size_t)(row + 8) * N + col);
                c00 += r0.x; c01 += r0.y; c10 += r1.x; c11 += r1.y;
            }
            if (doRelu) {
                c00 = fmaxf(c00, 0.f); c01 = fmaxf(c01, 0.f);
                c10 = fmaxf(c10, 0.f); c11 = fmaxf(c11, 0.f);
            }
            if (headStore) {
                int h_ = col >> 6, d_ = col & 63;
                int b0_ = row / SS_, s0_ = row % SS_;
                *(float2*)&C[(((size_t)(b0_ * HH + h_)) * SS_ + s0_) * 64 + d_] =
                    make_float2(c00, c01);
                int b1_ = (row + 8) / SS_, s1_ = (row + 8) % SS_;
                *(float2*)&C[(((size_t)(b1_ * HH + h_)) * SS_ + s1_) * 64 + d_] =
                    make_float2(c10, c11);
            } else {
                *(float2*)&C[(size_t)row * N + col] = make_float2(c00, c01);
                *(float2*)&C[(size_t)(row + 8) * N + col] = make_float2(c10, c11);
            }
        }
    }
}

__global__ __launch_bounds__(256, 2) void sgemm_kernel(
    const float* __restrict__ A, const float* __restrict__ W,
    const float* __restrict__ bias, const float* __restrict__ resid,
    float* __restrict__ C, int N, int K, int doRelu)
{
    extern __shared__ float smem[];
    gemm_tc_body(A, W, bias, resid, C, N, K, doRelu, 0,
                 blockIdx.y * 128, blockIdx.x * 128, smem);
}

__global__ __launch_bounds__(256, 2) void qkv_kernel(
    const float* __restrict__ A,
    const float* __restrict__ Wq, const float* __restrict__ bq,
    const float* __restrict__ Wk, const float* __restrict__ bk,
    const float* __restrict__ Wv, const float* __restrict__ bv,
    float* __restrict__ q, float* __restrict__ k, float* __restrict__ v)
{
    extern __shared__ float smem[];
    int sel = blockIdx.x >> 2;
    const float* W = (sel == 0) ? Wq : (sel == 1) ? Wk : Wv;
    const float* bias = (sel == 0) ? bq : (sel == 1) ? bk : bv;
    float* C = (sel == 0) ? q : (sel == 1) ? k : v;
    gemm_tc_body(A, W, bias, nullptr, C, DD, DD, 0, 1,
                 blockIdx.y * 128, (blockIdx.x & 3) * 128, smem);
}

// ------------------------------ qk: S = mask(Q K^T / 8), ldmatrix ----------
// grid (16 key-tiles, 16 row-tiles, 16 bh), 256 thr = 8 warps (4x2).
#define QKT 68
#define QK_TILE (128*QKT)
#define QK_SMEM_BYTES (2*QK_TILE*4)

__global__ __launch_bounds__(256, 2) void qk_kernel(
    const float* __restrict__ q, const float* __restrict__ k,
    float* __restrict__ attn)
{
    extern __shared__ float smem[];

    int tid = threadIdx.x;
    int w = tid >> 5, t = tid & 31;
    int wr = w >> 1, wc = w & 1;
    int tq = t >> 2, tr = t & 3;
    int bh = blockIdx.z, b_ = bh >> 3;
    int row0 = blockIdx.y * 128;
    int col0 = blockIdx.x * 128;

    const float* qptr = q + ((size_t)bh * SS_ + row0) * 64;
    const float* kptr = k + ((size_t)bh * SS_ + col0) * 64;
    const u32* mbits = g_maskbits + (size_t)b_ * SS_ * 64;
    u32 sb = s2u(smem);

#pragma unroll
    for (int i = 0; i < 8; i++) {
        int f = tid + i * 256;
        int r = f >> 4, c4 = (f & 15) * 4;
        cpa(sb + (u32)(r * QKT + c4) * 4u, qptr + (size_t)r * 64 + c4);
        cpa(sb + (u32)(QK_TILE + r * QKT + c4) * 4u, kptr + (size_t)r * 64 + c4);
    }
    CP_COMMIT();
    CP_WAIT0();
    __syncthreads();

    float4 acc[2][8];
#pragma unroll
    for (int f = 0; f < 2; f++)
#pragma unroll
        for (int nf = 0; nf < 8; nf++) acc[f][nf] = make_float4(0.f,0.f,0.f,0.f);

    // ldmatrix lane address bases
    // A (Q): matrices {rows 0-7, rows 8-15} x {cols +0, cols +4}
    u32 qbase0 = sb + (u32)((wr * 32 + (t & 15)) * QKT + 4 * (t >> 4)) * 4u;
    u32 qbase1 = qbase0 + (u32)(16 * QKT) * 4u;
    // B (K): matrices {n 0-7 col+0}, {n 0-7 col+4}, {n 8-15 col+0}, {n 8-15 col+4}
    int bn_row = wc * 64 + (t & 7) + ((t >> 4) << 3);
    int bcol = ((t >> 3) & 1) * 4;
    u32 kbase = sb + (u32)(QK_TILE + bn_row * QKT + bcol) * 4u;

#pragma unroll
    for (int j = 0; j < 8; j++) {
        u32 a0[2], a1[2], a2[2], a3[2];
        ldsm4(a0[0], a1[0], a2[0], a3[0], qbase0 + (u32)(j * 32));
        ldsm4(a0[1], a1[1], a2[1], a3[1], qbase1 + (u32)(j * 32));
#pragma unroll
        for (int p = 0; p < 4; p++) {
            u32 b0, b1, c0, c1;
            ldsm4(b0, b1, c0, c1, kbase + (u32)(p * 16 * QKT) * 4u + (u32)(j * 32));
#pragma unroll
            for (int f = 0; f < 2; f++) {
                mma8(acc[f][2 * p],     a0[f], a1[f], a2[f], a3[f], b0, b1);
                mma8(acc[f][2 * p + 1], a0[f], a1[f], a2[f], a3[f], c0, c1);
            }
        }
    }

#pragma unroll
    for (int f = 0; f < 2; f++) {
        int row = row0 + wr * 32 + f * 16 + tq;
#pragma unroll
        for (int nf = 0; nf < 8; nf++) {
            int col = col0 + wc * 64 + nf * 8 + tr * 2;
            float4 a = acc[f][nf];
            u32 w0 = mbits[(size_t)row * 64 + (col >> 5)];
            u32 w1 = mbits[(size_t)(row + 8) * 64 + (col >> 5)];
            int sh = col & 31;
            float2 s0, s1;
            s0.x = ((w0 >> sh) & 1u)       ? -1e9f : a.x * 0.125f;
            s0.y = ((w0 >> (sh + 1)) & 1u) ? -1e9f : a.y * 0.125f;
            s1.x = ((w1 >> sh) & 1u)       ? -1e9f : a.z * 0.125f;
            s1.y = ((w1 >> (sh + 1)) & 1u) ? -1e9f : a.w * 0.125f;
            *(float2*)&attn[((size_t)bh * SS_ + row) * SS_ + col] = s0;
            *(float2*)&attn[((size_t)bh * SS_ + row + 8) * SS_ + col] = s1;
        }
    }
}

// ------------------------------ softmax: normalize rows in place -----------
__global__ __launch_bounds__(256) void softmax_kernel(float* __restrict__ attn)
{
    int w = threadIdx.x >> 5, lane = threadIdx.x & 31;
    size_t row = (size_t)blockIdx.x * 8 + w;
    float4* p = (float4*)(attn + row * SS_);

    float4 v[16];
#pragma unroll
    for (int i = 0; i < 16; i++) v[i] = p[lane + i * 32];

    float mx = -1e30f;
#pragma unroll
    for (int i = 0; i < 16; i++)
        mx = fmaxf(mx, fmaxf(fmaxf(v[i].x, v[i].y), fmaxf(v[i].z, v[i].w)));
#pragma unroll
    for (int o = 16; o; o >>= 1)
        mx = fmaxf(mx, __shfl_xor_sync(0xffffffffu, mx, o));

    float sm = 0.f;
#pragma unroll
    for (int i = 0; i < 16; i++) {
        v[i].x = __expf(v[i].x - mx); v[i].y = __expf(v[i].y - mx);
        v[i].z = __expf(v[i].z - mx); v[i].w = __expf(v[i].w - mx);
        sm += v[i].x + v[i].y + v[i].z + v[i].w;
    }
#pragma unroll
    for (int o = 16; o; o >>= 1)
        sm += __shfl_xor_sync(0xffffffffu, sm, o);
    float inv = 1.f / sm;

#pragma unroll
    for (int i = 0; i < 16; i++) {
        v[i].x *= inv; v[i].y *= inv; v[i].z *= inv; v[i].w *= inv;
        p[lane + i * 32] = v[i];
    }
}

// ------------------------------ pv: ctx = attn @ V (4-stage cp.async) ------
#define PAST 20
#define PA_STG (128*PAST)
#define PVST 72
#define PV_STG (16*PVST)
#define PSTG_WORDS (PA_STG + PV_STG)
#define PV_SMEM_BYTES (4*PSTG_WORDS*4)

__device__ __forceinline__ void pv_issue(
    u32 sb, int c, const float* P, const float* V, int tid)
{
    if (c < 128) {
        int k0 = c * 16;
        u32 as = sb + (u32)((c & 3) * PSTG_WORDS) * 4u;
        u32 vs = as + PA_STG * 4u;
        int f0 = tid, f1 = tid + 256;
        cpa(as + (u32)((f0 >> 2) * PAST + (f0 & 3) * 4) * 4u,
            P + (size_t)(f0 >> 2) * SS_ + k0 + (f0 & 3) * 4);
        cpa(as + (u32)((f1 >> 2) * PAST + (f1 & 3) * 4) * 4u,
            P + (size_t)(f1 >> 2) * SS_ + k0 + (f1 & 3) * 4);
        cpa(vs + (u32)((tid >> 4) * PVST + (tid & 15) * 4) * 4u,
            V + (size_t)(k0 + (tid >> 4)) * 64 + (tid & 15) * 4);
    }
    CP_COMMIT();
}

__global__ __launch_bounds__(256, 2) void pv_kernel(
    const float* __restrict__ attn, const float* __restrict__ v,
    float* __restrict__ ctx)
{
    extern __shared__ float smem[];
    int tid = threadIdx.x;
    int w = tid >> 5, t = tid & 31;
    int tq = t >> 2, tr = t & 3;
    int bh = blockIdx.y, b_ = bh >> 3, h_ = bh & 7;
    int row0 = blockIdx.x * 128;
    u32 sb = s2u(smem);

    const float* P = attn + (size_t)bh * SS_ * SS_ + (size_t)row0 * SS_;
    const float* V = v + (size_t)bh * SS_ * 64;

    float4 acc[8];
#pragma unroll
    for (int nf = 0; nf < 8; nf++) acc[nf] = make_float4(0.f,0.f,0.f,0.f);

    pv_issue(sb, 0, P, V, tid);
    pv_issue(sb, 1, P, V, tid);
    pv_issue(sb, 2, P, V, tid);

    for (int i = 0; i < 128; i++) {
        CP_WAIT2();
        __syncthreads();
        pv_issue(sb, i + 3, P, V, tid);

        const float* As = smem + (i & 3) * PSTG_WORDS;
        const float* Vs = As + PA_STG;
        int rb = w * 16;
#pragma unroll
        for (int kh = 0; kh < 2; kh++) {
            u32 a0 = fu(As[(rb + tq) * PAST + kh * 8 + tr]);
            u32 a1 = fu(As[(rb + tq + 8) * PAST + kh * 8 + tr]);
            u32 a2 = fu(As[(rb + tq) * PAST + kh * 8 + tr + 4]);
            u32 a3 = fu(As[(rb + tq + 8) * PAST + kh * 8 + tr + 4]);
#pragma unroll
            for (int nf = 0; nf < 8; nf++) {
                int n = nf * 8 + tq;
                u32 b0 = fu(Vs[(kh * 8 + tr) * PVST + n]);
                u32 b1 = fu(Vs[(kh * 8 + tr + 4) * PVST + n]);
                mma8(acc[nf], a0, a1, a2, a3, b0, b1);
            }
        }
    }

    int r0 = row0 + w * 16 + tq;
#pragma unroll
    for (int nf = 0; nf < 8; nf++) {
        int col = h_ * 64 + nf * 8 + tr * 2;
        *(float2*)&ctx[((size_t)(b_ * SS_ + r0)) * DD + col] =
            make_float2(acc[nf].x, acc[nf].y);
        *(float2*)&ctx[((size_t)(b_ * SS_ + r0 + 8)) * DD + col] =
            make_float2(acc[nf].z, acc[nf].w);
    }
}

// ------------------------------ layernorm ----------------------------------
__global__ __launch_bounds__(128) void ln_kernel(
    const float* __restrict__ x, const float* __restrict__ gamma,
    const float* __restrict__ beta, float* __restrict__ out)
{
    int row = blockIdx.x;
    int tid = threadIdx.x;
    __shared__ float red[4];
    float4 v = ((const float4*)(x + (size_t)row * DD))[tid];
    float s = v.x + v.y + v.z + v.w;
#pragma unroll
    for (int o = 16; o; o >>= 1) s += __shfl_xor_sync(0xffffffffu, s, o);
    if ((tid & 31) == 0) red[tid >> 5] = s;
    __syncthreads();
    float mu = (red[0] + red[1] + red[2] + red[3]) * (1.f / DD);
    float dx = v.x - mu, dy = v.y - mu, dz = v.z - mu, dw = v.w - mu;
    float s2 = dx * dx + dy * dy + dz * dz + dw * dw;
#pragma unroll
    for (int o = 16; o; o >>= 1) s2 += __shfl_xor_sync(0xffffffffu, s2, o);
    __syncthreads();
    if ((tid & 31) == 0) red[tid >> 5] = s2;
    __syncthreads();
    float var = (red[0] + red[1] + red[2] + red[3]) * (1.f / DD);
    float inv = rsqrtf(var + EPS);
    float4 gg = ((const float4*)gamma)[tid];
    float4 bb = ((const float4*)beta)[tid];
    float4 o;
    o.x = dx * inv * gg.x + bb.x;
    o.y = dy * inv * gg.y + bb.y;
    o.z = dz * inv * gg.z + bb.z;
    o.w = dw * inv * gg.w + bb.w;
    *(float4*)(out + (size_t)row * DD + tid * 4) = o;
}

// ------------------------------ launch -------------------------------------
extern "C" void kernel_launch(void* const* d_in, const int* in_sizes, int n_in,
                              void* d_out, int out_size)
{
    const float* x   = (const float*)d_in[0];
    const void*  mask = d_in[1];
    const float* Wq  = (const float*)d_in[2];
    const float* bq  = (const float*)d_in[3];
    const float* Wk  = (const float*)d_in[4];
    const float* bk  = (const float*)d_in[5];
    const float* Wv  = (const float*)d_in[6];
    const float* bv  = (const float*)d_in[7];
    const float* Wo  = (const float*)d_in[8];
    const float* bo  = (const float*)d_in[9];
    const float* ln1g = (const float*)d_in[10];
    const float* ln1b = (const float*)d_in[11];
    const float* W1  = (const float*)d_in[12];
    const float* b1  = (const float*)d_in[13];
    const float* W2  = (const float*)d_in[14];
    const float* b2  = (const float*)d_in[15];
    const float* ln2g = (const float*)d_in[16];
    const float* ln2b = (const float*)d_in[17];

    float* out = (float*)d_out;
    const long OUT_ELEMS = (long)BB * SS_ * DD;
    const long ATTN_ELEMS = (long)BB * HH * SS_ * SS_;

    float *qp, *kp, *vp, *ctxp, *t1p, *aop, *hp, *t2p, *attnScratch;
    cudaGetSymbolAddress((void**)&qp, g_qb);
    cudaGetSymbolAddress((void**)&kp, g_kb);
    cudaGetSymbolAddress((void**)&vp, g_vb);
    cudaGetSymbolAddress((void**)&ctxp, g_ctx);
    cudaGetSymbolAddress((void**)&t1p, g_t1);
    cudaGetSymbolAddress((void**)&aop, g_ao);
    cudaGetSymbolAddress((void**)&hp, g_h);
    cudaGetSymbolAddress((void**)&t2p, g_t2);
    cudaGetSymbolAddress((void**)&attnScratch, g_attn);

    float* attn_ptr = ((long)out_size >= OUT_ELEMS + ATTN_ELEMS)
                        ? (out + OUT_ELEMS) : attnScratch;

    cudaFuncSetAttribute(sgemm_kernel,
                         cudaFuncAttributeMaxDynamicSharedMemorySize,
                         GEMM_SMEM_BYTES);
    cudaFuncSetAttribute(qkv_kernel,
                         cudaFuncAttributeMaxDynamicSharedMemorySize,
                         GEMM_SMEM_BYTES);
    cudaFuncSetAttribute(qk_kernel,
                         cudaFuncAttributeMaxDynamicSharedMemorySize,
                         QK_SMEM_BYTES);
    cudaFuncSetAttribute(pv_kernel,
                         cudaFuncAttributeMaxDynamicSharedMemorySize,
                         PV_SMEM_BYTES);

    dim3 blk(256);
    detect_mask_kernel<<<1, 32>>>((const unsigned int*)mask);
    pack_mask_kernel<<<BB * SS_ * 64 / 256, blk>>>(mask);
    qkv_kernel<<<dim3(12, 32), blk, GEMM_SMEM_BYTES>>>(
        x, Wq, bq, Wk, bk, Wv, bv, qp, kp, vp);
    qk_kernel<<<dim3(16, 16, BB * HH), blk, QK_SMEM_BYTES>>>(
        qp, kp, attn_ptr);
    softmax_kernel<<<BB * HH * SS_ / 8, blk>>>(attn_ptr);
    pv_kernel<<<dim3(16, BB * HH), blk, PV_SMEM_BYTES>>>(attn_ptr, vp, ctxp);
    sgemm_kernel<<<dim3(4, 32), blk, GEMM_SMEM_BYTES>>>(
        ctxp, Wo, bo, x, t1p, DD, DD, 0);
    ln_kernel<<<NTOK, 128>>>(t1p, ln1g, ln1b, aop);
    sgemm_kernel<<<dim3(16, 32), blk, GEMM_SMEM_BYTES>>>(
        aop, W1, b1, nullptr, hp, DFF, DD, 1);
    sgemm_kernel<<<dim3(4, 32), blk, GEMM_SMEM_BYTES>>>(
        hp, W2, b2, aop, t2p, DD, DFF, 0);
    ln_kernel<<<NTOK, 128>>>(t2p, ln2g, ln2b, out);
}

// round 17
// speedup vs baseline: 1.0301x; 1.0242x over previous
#include <cuda_runtime.h>
#include <math.h>

#define BB 2
#define SS_ 2048
#define DD 512
#define HH 8
#define DFF 2048
#define NTOK (BB*SS_)          // 4096
#define EPS 1e-5f

typedef unsigned long long ull;
typedef unsigned int u32;

// tf32 mma: HW reads high 19 bits; pass raw fp32 bits (CUTLASS-style).
__device__ __forceinline__ u32 fu(float x) { return __float_as_uint(x); }
__device__ __forceinline__ void mma8(float4& d, u32 a0, u32 a1, u32 a2, u32 a3,
                                     u32 b0, u32 b1) {
    asm("mma.sync.aligned.m16n8k8.row.col.f32.tf32.tf32.f32 "
        "{%0,%1,%2,%3},{%4,%5,%6,%7},{%8,%9},{%0,%1,%2,%3};"
        : "+f"(d.x), "+f"(d.y), "+f"(d.z), "+f"(d.w)
        : "r"(a0), "r"(a1), "r"(a2), "r"(a3), "r"(b0), "r"(b1));
}
__device__ __forceinline__ u32 s2u(const void* p) {
    return (u32)__cvta_generic_to_shared(p);
}
__device__ __forceinline__ void cpa(u32 dst, const void* src) {
    asm volatile("cp.async.cg.shared.global [%0], [%1], 16;"
                 :: "r"(dst), "l"(src));
}
#define CP_COMMIT() asm volatile("cp.async.commit_group;" ::: "memory")
#define CP_WAIT2()  asm volatile("cp.async.wait_group 2;" ::: "memory")
#define CP_WAIT0()  asm volatile("cp.async.wait_group 0;" ::: "memory")

// ------------------------------ scratch ------------------------------------
__device__ float g_qb[BB*HH*SS_*64];
__device__ float g_kb[BB*HH*SS_*64];
__device__ float g_vb[BB*HH*SS_*64];
__device__ float g_ctx[NTOK*DD];
__device__ float g_t1[NTOK*DD];
__device__ float g_ao[NTOK*DD];
__device__ float g_h[NTOK*DFF];
__device__ float g_t2[NTOK*DD];
__device__ float g_part[2*NTOK*DD];               // K-split partials
__device__ float g_attn[(size_t)BB*HH*SS_*SS_];   // fallback if attn not in d_out
__device__ u32   g_maskbits[BB*SS_*64];           // 1 MB packed mask bits
__device__ int   g_maskmode;               // 0 = int32 mask, 1 = uint8 mask

__global__ void detect_mask_kernel(const unsigned int* __restrict__ m)
{
    if (threadIdx.x == 0 && blockIdx.x == 0) {
        int mode = 0;
        for (int i = 0; i < 4096; i++) {
            if (m[i] > 1u) { mode = 1; break; }
        }
        g_maskmode = mode;
    }
}

// pack mask (int32 or uint8) into bits
__global__ __launch_bounds__(256) void pack_mask_kernel(const void* __restrict__ mask)
{
    int i = blockIdx.x * 256 + threadIdx.x;        // 0 .. BB*SS_*64-1
    int mm = g_maskmode;
    u32 b = 0;
    if (mm == 0) {
        const int4* p = (const int4*)mask + (size_t)i * 8;
#pragma unroll
        for (int j = 0; j < 8; j++) {
            int4 m = p[j];
            b |= (m.x ? 1u : 0u) << (j * 4 + 0);
            b |= (m.y ? 1u : 0u) << (j * 4 + 1);
            b |= (m.z ? 1u : 0u) << (j * 4 + 2);
            b |= (m.w ? 1u : 0u) << (j * 4 + 3);
        }
    } else {
        const uchar4* p = (const uchar4*)mask + (size_t)i * 8;
#pragma unroll
        for (int j = 0; j < 8; j++) {
            uchar4 m = p[j];
            b |= (m.x ? 1u : 0u) << (j * 4 + 0);
            b |= (m.y ? 1u : 0u) << (j * 4 + 1);
            b |= (m.z ? 1u : 0u) << (j * 4 + 2);
            b |= (m.w ? 1u : 0u) << (j * 4 + 3);
        }
    }
    g_maskbits[i] = b;
}

// ------------------------------ tf32 GEMM (4-stage cp.async, N=128) --------
#define AST 20
#define WST 136
#define A_STG (128*AST)
#define W_STG (16*WST)
#define STG_WORDS (A_STG + W_STG)
#define GEMM_SMEM_BYTES (4*STG_WORDS*4)

__device__ __forceinline__ void gemm_issue(
    u32 sb, int c, int NCH, const float* A, const float* W,
    int Kstride, int N, int rowBase, int colBase, int tid)
{
    if (c < NCH) {
        int k0 = c * 16;
        u32 as = sb + (u32)((c & 3) * STG_WORDS) * 4u;
        u32 ws = as + A_STG * 4u;
        int f0 = tid, f1 = tid + 256;
        cpa(as + (u32)((f0 >> 2) * AST + (f0 & 3) * 4) * 4u,
            A + (size_t)(rowBase + (f0 >> 2)) * Kstride + k0 + (f0 & 3) * 4);
        cpa(as + (u32)((f1 >> 2) * AST + (f1 & 3) * 4) * 4u,
            A + (size_t)(rowBase + (f1 >> 2)) * Kstride + k0 + (f1 & 3) * 4);
        cpa(ws + (u32)((f0 >> 5) * WST + (f0 & 31) * 4) * 4u,
            W + (size_t)(k0 + (f0 >> 5)) * N + colBase + (f0 & 31) * 4);
        cpa(ws + (u32)((f1 >> 5) * WST + (f1 & 31) * 4) * 4u,
            W + (size_t)(k0 + (f1 >> 5)) * N + colBase + (f1 & 31) * 4);
    }
    CP_COMMIT();
}

// bias may be null (raw partial output). resid may be null.
__device__ __forceinline__ void gemm_tc_body(
    const float* __restrict__ A, const float* __restrict__ W,
    const float* __restrict__ bias, const float* __restrict__ resid,
    float* __restrict__ C, int N, int K, int Kstride, int doRelu, int headStore,
    int rowBase, int colBase, float* smem)
{
    int tid = threadIdx.x;
    int w = tid >> 5, t = tid & 31;
    int wr = w >> 1, wc = w & 1;
    int tq = t >> 2, tr = t & 3;
    u32 sb = s2u(smem);
    int NCH = K >> 4;

    float4 acc[2][8];
#pragma unroll
    for (int f = 0; f < 2; f++)
#pragma unroll
        for (int nf = 0; nf < 8; nf++) acc[f][nf] = make_float4(0.f,0.f,0.f,0.f);

    gemm_issue(sb, 0, NCH, A, W, Kstride, N, rowBase, colBase, tid);
    gemm_issue(sb, 1, NCH, A, W, Kstride, N, rowBase, colBase, tid);
    gemm_issue(sb, 2, NCH, A, W, Kstride, N, rowBase, colBase, tid);

    for (int i = 0; i < NCH; i++) {
        CP_WAIT2();
        __syncthreads();
        gemm_issue(sb, i + 3, NCH, A, W, Kstride, N, rowBase, colBase, tid);

        const float* As = smem + (i & 3) * STG_WORDS;
        const float* Ws = As + A_STG;
#pragma unroll
        for (int kh = 0; kh < 2; kh++) {
            u32 a0[2], a1[2], a2[2], a3[2];
#pragma unroll
            for (int f = 0; f < 2; f++) {
                int rb = wr * 32 + f * 16;
                a0[f] = fu(As[(rb + tq) * AST + kh * 8 + tr]);
                a1[f] = fu(As[(rb + tq + 8) * AST + kh * 8 + tr]);
                a2[f] = fu(As[(rb + tq) * AST + kh * 8 + tr + 4]);
                a3[f] = fu(As[(rb + tq + 8) * AST + kh * 8 + tr + 4]);
            }
#pragma unroll
            for (int nf = 0; nf < 8; nf++) {
                int n = wc * 64 + nf * 8 + tq;
                u32 b0 = fu(Ws[(kh * 8 + tr) * WST + n]);
                u32 b1 = fu(Ws[(kh * 8 + tr + 4) * WST + n]);
#pragma unroll
                for (int f = 0; f < 2; f++)
                    mma8(acc[f][nf], a0[f], a1[f], a2[f], a3[f], b0, b1);
            }
        }
    }

#pragma unroll
    for (int f = 0; f < 2; f++) {
        int row = rowBase + wr * 32 + f * 16 + tq;
#pragma unroll
        for (int nf = 0; nf < 8; nf++) {
            int col = colBase + wc * 64 + nf * 8 + tr * 2;
            float b0 = bias ? bias[col] : 0.f;
            float b1 = bias ? bias[col + 1] : 0.f;
            float c00 = acc[f][nf].x + b0, c01 = acc[f][nf].y + b1;
            float c10 = acc[f][nf].z + b0, c11 = acc[f][nf].w + b1;
            if (resid) {
                float2 r0 = *(const float2*)(resid + (size_t)row * N + col);
                float2 r1 = *(const float2*)(resid + (size_t)(row + 8) * N + col);
                c00 += r0.x; c01 += r0.y; c10 += r1.x; c11 += r1.y;
            }
            if (doRelu) {
                c00 = fmaxf(c00, 0.f); c01 = fmaxf(c01, 0.f);
                c10 = fmaxf(c10, 0.f); c11 = fmaxf(c11, 0.f);
            }
            if (headStore) {
                int h_ = col >> 6, d_ = col & 63;
                int b0_ = row / SS_, s0_ = row % SS_;
                *(float2*)&C[(((size_t)(b0_ * HH + h_)) * SS_ + s0_) * 64 + d_] =
                    make_float2(c00, c01);
                int b1_ = (row + 8) / SS_, s1_ = (row + 8) % SS_;
                *(float2*)&C[(((size_t)(b1_ * HH + h_)) * SS_ + s1_) * 64 + d_] =
                    make_float2(c10, c11);
            } else {
                *(float2*)&C[(size_t)row * N + col] = make_float2(c00, c01);
                *(float2*)&C[(size_t)(row + 8) * N + col] = make_float2(c10, c11);
            }
        }
    }
}

__global__ __launch_bounds__(256, 2) void sgemm_kernel(
    const float* __restrict__ A, const float* __restrict__ W,
    const float* __restrict__ bias, const float* __restrict__ resid,
    float* __restrict__ C, int N, int K, int doRelu)
{
    extern __shared__ float smem[];
    gemm_tc_body(A, W, bias, resid, C, N, K, K, doRelu, 0,
                 blockIdx.y * 128, blockIdx.x * 128, smem);
}

// K-split partial GEMM: z = k-half; writes raw partials to parts[z].
__global__ __launch_bounds__(256, 2) void sgemm_ksplit_kernel(
    const float* __restrict__ A, const float* __restrict__ W,
    float* __restrict__ parts, int N, int K, int KH)
{
    extern __shared__ float smem[];
    int z = blockIdx.z;
    gemm_tc_body(A + (size_t)z * KH, W + (size_t)z * KH * N, nullptr, nullptr,
                 parts + (size_t)z * NTOK * N, N, KH, K, 0, 0,
                 blockIdx.y * 128, blockIdx.x * 128, smem);
}

// out = p0 + p1 + bias + resid  (elementwise over [NTOK, N=512])
__global__ __launch_bounds__(256) void combine2_kernel(
    const float* __restrict__ parts, const float* __restrict__ bias,
    const float* __restrict__ resid, float* __restrict__ out)
{
    int i = blockIdx.x * 256 + threadIdx.x;        // float4 index
    const float4* p0 = (const float4*)parts;
    const float4* p1 = (const float4*)(parts + (size_t)NTOK * DD);
    float4 a = p0[i], b = p1[i];
    float4 r = ((const float4*)resid)[i];
    float4 g = ((const float4*)bias)[(i & (DD / 4 - 1))];
    float4 o;
    o.x = a.x + b.x + g.x + r.x;
    o.y = a.y + b.y + g.y + r.y;
    o.z = a.z + b.z + g.z + r.z;
    o.w = a.w + b.w + g.w + r.w;
    ((float4*)out)[i] = o;
}

__global__ __launch_bounds__(256, 2) void qkv_kernel(
    const float* __restrict__ A,
    const float* __restrict__ Wq, const float* __restrict__ bq,
    const float* __restrict__ Wk, const float* __restrict__ bk,
    const float* __restrict__ Wv, const float* __restrict__ bv,
    float* __restrict__ q, float* __restrict__ k, float* __restrict__ v)
{
    extern __shared__ float smem[];
    int sel = blockIdx.x >> 2;
    const float* W = (sel == 0) ? Wq : (sel == 1) ? Wk : Wv;
    const float* bias = (sel == 0) ? bq : (sel == 1) ? bk : bv;
    float* C = (sel == 0) ? q : (sel == 1) ? k : v;
    gemm_tc_body(A, W, bias, nullptr, C, DD, DD, DD, 0, 1,
                 blockIdx.y * 128, (blockIdx.x & 3) * 128, smem);
}

// ------------------------------ qk: S = mask(Q K^T / 8) --------------------
// grid (16 key-tiles, 16 row-tiles, 16 bh), 256 thr = 8 warps (4x2).
#define QKT 68
#define QK_TILE (128*QKT)
#define QK_SMEM_BYTES (2*QK_TILE*4)

__global__ __launch_bounds__(256, 2) void qk_kernel(
    const float* __restrict__ q, const float* __restrict__ k,
    float* __restrict__ attn)
{
    extern __shared__ float smem[];
    float* Qs = smem;
    float* Ks = smem + QK_TILE;

    int tid = threadIdx.x;
    int w = tid >> 5, t = tid & 31;
    int wr = w >> 1, wc = w & 1;
    int tq = t >> 2, tr = t & 3;
    int bh = blockIdx.z, b_ = bh >> 3;
    int row0 = blockIdx.y * 128;
    int col0 = blockIdx.x * 128;

    const float* qptr = q + ((size_t)bh * SS_ + row0) * 64;
    const float* kptr = k + ((size_t)bh * SS_ + col0) * 64;
    const u32* mbits = g_maskbits + (size_t)b_ * SS_ * 64;
    u32 sb = s2u(smem);

#pragma unroll
    for (int i = 0; i < 8; i++) {
        int f = tid + i * 256;
        int r = f >> 4, c4 = (f & 15) * 4;
        cpa(sb + (u32)(r * QKT + c4) * 4u, qptr + (size_t)r * 64 + c4);
        cpa(sb + (u32)(QK_TILE + r * QKT + c4) * 4u, kptr + (size_t)r * 64 + c4);
    }
    CP_COMMIT();
    CP_WAIT0();
    __syncthreads();

    float4 acc[2][8];
#pragma unroll
    for (int f = 0; f < 2; f++)
#pragma unroll
        for (int nf = 0; nf < 8; nf++) acc[f][nf] = make_float4(0.f,0.f,0.f,0.f);

#pragma unroll
    for (int j = 0; j < 8; j++) {
        u32 a0[2], a1[2], a2[2], a3[2];
#pragma unroll
        for (int f = 0; f < 2; f++) {
            int rb = wr * 32 + f * 16;
            a0[f] = fu(Qs[(rb + tq) * QKT + j * 8 + tr]);
            a1[f] = fu(Qs[(rb + tq + 8) * QKT + j * 8 + tr]);
            a2[f] = fu(Qs[(rb + tq) * QKT + j * 8 + tr + 4]);
            a3[f] = fu(Qs[(rb + tq + 8) * QKT + j * 8 + tr + 4]);
        }
#pragma unroll
        for (int nf = 0; nf < 8; nf++) {
            int n = wc * 64 + nf * 8 + tq;
            u32 b0 = fu(Ks[n * QKT + j * 8 + tr]);
            u32 b1 = fu(Ks[n * QKT + j * 8 + tr + 4]);
#pragma unroll
            for (int f = 0; f < 2; f++)
                mma8(acc[f][nf], a0[f], a1[f], a2[f], a3[f], b0, b1);
        }
    }

#pragma unroll
    for (int f = 0; f < 2; f++) {
        int row = row0 + wr * 32 + f * 16 + tq;
#pragma unroll
        for (int nf = 0; nf < 8; nf++) {
            int col = col0 + wc * 64 + nf * 8 + tr * 2;
            float4 a = acc[f][nf];
            u32 w0 = mbits[(size_t)row * 64 + (col >> 5)];
            u32 w1 = mbits[(size_t)(row + 8) * 64 + (col >> 5)];
            int sh = col & 31;
            float2 s0, s1;
            s0.x = ((w0 >> sh) & 1u)       ? -1e9f : a.x * 0.125f;
            s0.y = ((w0 >> (sh + 1)) & 1u) ? -1e9f : a.y * 0.125f;
            s1.x = ((w1 >> sh) & 1u)       ? -1e9f : a.z * 0.125f;
            s1.y = ((w1 >> (sh + 1)) & 1u) ? -1e9f : a.w * 0.125f;
            *(float2*)&attn[((size_t)bh * SS_ + row) * SS_ + col] = s0;
            *(float2*)&attn[((size_t)bh * SS_ + row + 8) * SS_ + col] = s1;
        }
    }
}

// ------------------------------ softmax: normalize rows in place -----------
__global__ __launch_bounds__(256) void softmax_kernel(float* __restrict__ attn)
{
    int w = threadIdx.x >> 5, lane = threadIdx.x & 31;
    size_t row = (size_t)blockIdx.x * 8 + w;
    float4* p = (float4*)(attn + row * SS_);

    float4 v[16];
#pragma unroll
    for (int i = 0; i < 16; i++) v[i] = p[lane + i * 32];

    float mx = -1e30f;
#pragma unroll
    for (int i = 0; i < 16; i++)
        mx = fmaxf(mx, fmaxf(fmaxf(v[i].x, v[i].y), fmaxf(v[i].z, v[i].w)));
#pragma unroll
    for (int o = 16; o; o >>= 1)
        mx = fmaxf(mx, __shfl_xor_sync(0xffffffffu, mx, o));

    float sm = 0.f;
#pragma unroll
    for (int i = 0; i < 16; i++) {
        v[i].x = __expf(v[i].x - mx); v[i].y = __expf(v[i].y - mx);
        v[i].z = __expf(v[i].z - mx); v[i].w = __expf(v[i].w - mx);
        sm += v[i].x + v[i].y + v[i].z + v[i].w;
    }
#pragma unroll
    for (int o = 16; o; o >>= 1)
        sm += __shfl_xor_sync(0xffffffffu, sm, o);
    float inv = 1.f / sm;

#pragma unroll
    for (int i = 0; i < 16; i++) {
        v[i].x *= inv; v[i].y *= inv; v[i].z *= inv; v[i].w *= inv;
        p[lane + i * 32] = v[i];
    }
}

// ------------------------------ pv: ctx = attn @ V (4-stage cp.async) ------
// 8 warps as 4x2: warp rows wr*32 (2 f-blocks), cols wc*32 (4 nf).
#define PAST 20
#define PA_STG (128*PAST)
#define PVST 72
#define PV_STG (16*PVST)
#define PSTG_WORDS (PA_STG + PV_STG)
#define PV_SMEM_BYTES (4*PSTG_WORDS*4)

__device__ __forceinline__ void pv_issue(
    u32 sb, int c, const float* P, const float* V, int tid)
{
    if (c < 128) {
        int k0 = c * 16;
        u32 as = sb + (u32)((c & 3) * PSTG_WORDS) * 4u;
        u32 vs = as + PA_STG * 4u;
        int f0 = tid, f1 = tid + 256;
        cpa(as + (u32)((f0 >> 2) * PAST + (f0 & 3) * 4) * 4u,
            P + (size_t)(f0 >> 2) * SS_ + k0 + (f0 & 3) * 4);
        cpa(as + (u32)((f1 >> 2) * PAST + (f1 & 3) * 4) * 4u,
            P + (size_t)(f1 >> 2) * SS_ + k0 + (f1 & 3) * 4);
        cpa(vs + (u32)((tid >> 4) * PVST + (tid & 15) * 4) * 4u,
            V + (size_t)(k0 + (tid >> 4)) * 64 + (tid & 15) * 4);
    }
    CP_COMMIT();
}

__global__ __launch_bounds__(256, 2) void pv_kernel(
    const float* __restrict__ attn, const float* __restrict__ v,
    float* __restrict__ ctx)
{
    extern __shared__ float smem[];
    int tid = threadIdx.x;
    int w = tid >> 5, t = tid & 31;
    int wr = w >> 1, wc = w & 1;
    int tq = t >> 2, tr = t & 3;
    int bh = blockIdx.y, b_ = bh >> 3, h_ = bh & 7;
    int row0 = blockIdx.x * 128;
    u32 sb = s2u(smem);

    const float* P = attn + (size_t)bh * SS_ * SS_ + (size_t)row0 * SS_;
    const float* V = v + (size_t)bh * SS_ * 64;

    float4 acc[2][4];
#pragma unroll
    for (int f = 0; f < 2; f++)
#pragma unroll
        for (int nf = 0; nf < 4; nf++) acc[f][nf] = make_float4(0.f,0.f,0.f,0.f);

    pv_issue(sb, 0, P, V, tid);
    pv_issue(sb, 1, P, V, tid);
    pv_issue(sb, 2, P, V, tid);

    for (int i = 0; i < 128; i++) {
        CP_WAIT2();
        __syncthreads();
        pv_issue(sb, i + 3, P, V, tid);

        const float* As = smem + (i & 3) * PSTG_WORDS;
        const float* Vs = As + PA_STG;
#pragma unroll
        for (int kh = 0; kh < 2; kh++) {
            u32 a0[2], a1[2], a2[2], a3[2];
#pragma unroll
            for (int f = 0; f < 2; f++) {
                int rb = wr * 32 + f * 16;
                a0[f] = fu(As[(rb + tq) * PAST + kh * 8 + tr]);
                a1[f] = fu(As[(rb + tq + 8) * PAST + kh * 8 + tr]);
                a2[f] = fu(As[(rb + tq) * PAST + kh * 8 + tr + 4]);
                a3[f] = fu(As[(rb + tq + 8) * PAST + kh * 8 + tr + 4]);
            }
#pragma unroll
            for (int nf = 0; nf < 4; nf++) {
                int n = wc * 32 + nf * 8 + tq;
                u32 b0 = fu(Vs[(kh * 8 + tr) * PVST + n]);
                u32 b1 = fu(Vs[(kh * 8 + tr + 4) * PVST + n]);
#pragma unroll
                for (int f = 0; f < 2; f++)
                    mma8(acc[f][nf], a0[f], a1[f], a2[f], a3[f], b0, b1);
            }
        }
    }

#pragma unroll
    for (int f = 0; f < 2; f++) {
        int r0 = row0 + wr * 32 + f * 16 + tq;
#pragma unroll
        for (int nf = 0; nf < 4; nf++) {
            int col = h_ * 64 + wc * 32 + nf * 8 + tr * 2;
            *(float2*)&ctx[((size_t)(b_ * SS_ + r0)) * DD + col] =
                make_float2(acc[f][nf].x, acc[f][nf].y);
            *(float2*)&ctx[((size_t)(b_ * SS_ + r0 + 8)) * DD + col] =
                make_float2(acc[f][nf].z, acc[f][nf].w);
        }
    }
}

// ------------------------------ layernorm ----------------------------------
__global__ __launch_bounds__(128) void ln_kernel(
    const float* __restrict__ x, const float* __restrict__ gamma,
    const float* __restrict__ beta, float* __restrict__ out)
{
    int row = blockIdx.x;
    int tid = threadIdx.x;
    __shared__ float red[4];
    float4 v = ((const float4*)(x + (size_t)row * DD))[tid];
    float s = v.x + v.y + v.z + v.w;
#pragma unroll
    for (int o = 16; o; o >>= 1) s += __shfl_xor_sync(0xffffffffu, s, o);
    if ((tid & 31) == 0) red[tid >> 5] = s;
    __syncthreads();
    float mu = (red[0] + red[1] + red[2] + red[3]) * (1.f / DD);
    float dx = v.x - mu, dy = v.y - mu, dz = v.z - mu, dw = v.w - mu;
    float s2 = dx * dx + dy * dy + dz * dz + dw * dw;
#pragma unroll
    for (int o = 16; o; o >>= 1) s2 += __shfl_xor_sync(0xffffffffu, s2, o);
    __syncthreads();
    if ((tid & 31) == 0) red[tid >> 5] = s2;
    __syncthreads();
    float var = (red[0] + red[1] + red[2] + red[3]) * (1.f / DD);
    float inv = rsqrtf(var + EPS);
    float4 gg = ((const float4*)gamma)[tid];
    float4 bb = ((const float4*)beta)[tid];
    float4 o;
    o.x = dx * inv * gg.x + bb.x;
    o.y = dy * inv * gg.y + bb.y;
    o.z = dz * inv * gg.z + bb.z;
    o.w = dw * inv * gg.w + bb.w;
    *(float4*)(out + (size_t)row * DD + tid * 4) = o;
}

// ------------------------------ launch -------------------------------------
extern "C" void kernel_launch(void* const* d_in, const int* in_sizes, int n_in,
                              void* d_out, int out_size)
{
    const float* x   = (const float*)d_in[0];
    const void*  mask = d_in[1];
    const float* Wq  = (const float*)d_in[2];
    const float* bq  = (const float*)d_in[3];
    const float* Wk  = (const float*)d_in[4];
    const float* bk  = (const float*)d_in[5];
    const float* Wv  = (const float*)d_in[6];
    const float* bv  = (const float*)d_in[7];
    const float* Wo  = (const float*)d_in[8];
    const float* bo  = (const float*)d_in[9];
    const float* ln1g = (const float*)d_in[10];
    const float* ln1b = (const float*)d_in[11];
    const float* W1  = (const float*)d_in[12];
    const float* b1  = (const float*)d_in[13];
    const float* W2  = (const float*)d_in[14];
    const float* b2  = (const float*)d_in[15];
    const float* ln2g = (const float*)d_in[16];
    const float* ln2b = (const float*)d_in[17];

    float* out = (float*)d_out;
    const long OUT_ELEMS = (long)BB * SS_ * DD;
    const long ATTN_ELEMS = (long)BB * HH * SS_ * SS_;

    float *qp, *kp, *vp, *ctxp, *t1p, *aop, *hp, *t2p, *partp, *attnScratch;
    cudaGetSymbolAddress((void**)&qp, g_qb);
    cudaGetSymbolAddress((void**)&kp, g_kb);
    cudaGetSymbolAddress((void**)&vp, g_vb);
    cudaGetSymbolAddress((void**)&ctxp, g_ctx);
    cudaGetSymbolAddress((void**)&t1p, g_t1);
    cudaGetSymbolAddress((void**)&aop, g_ao);
    cudaGetSymbolAddress((void**)&hp, g_h);
    cudaGetSymbolAddress((void**)&t2p, g_t2);
    cudaGetSymbolAddress((void**)&partp, g_part);
    cudaGetSymbolAddress((void**)&attnScratch, g_attn);

    float* attn_ptr = ((long)out_size >= OUT_ELEMS + ATTN_ELEMS)
                        ? (out + OUT_ELEMS) : attnScratch;

    cudaFuncSetAttribute(sgemm_kernel,
                         cudaFuncAttributeMaxDynamicSharedMemorySize,
                         GEMM_SMEM_BYTES);
    cudaFuncSetAttribute(sgemm_ksplit_kernel,
                         cudaFuncAttributeMaxDynamicSharedMemorySize,
                         GEMM_SMEM_BYTES);
    cudaFuncSetAttribute(qkv_kernel,
                         cudaFuncAttributeMaxDynamicSharedMemorySize,
                         GEMM_SMEM_BYTES);
    cudaFuncSetAttribute(qk_kernel,
                         cudaFuncAttributeMaxDynamicSharedMemorySize,
                         QK_SMEM_BYTES);
    cudaFuncSetAttribute(pv_kernel,
                         cudaFuncAttributeMaxDynamicSharedMemorySize,
                         PV_SMEM_BYTES);

    dim3 blk(256);
    detect_mask_kernel<<<1, 32>>>((const unsigned int*)mask);
    pack_mask_kernel<<<BB * SS_ * 64 / 256, blk>>>(mask);
    qkv_kernel<<<dim3(12, 32), blk, GEMM_SMEM_BYTES>>>(
        x, Wq, bq, Wk, bk, Wv, bv, qp, kp, vp);
    qk_kernel<<<dim3(16, 16, BB * HH), blk, QK_SMEM_BYTES>>>(
        qp, kp, attn_ptr);
    softmax_kernel<<<BB * HH * SS_ / 8, blk>>>(attn_ptr);
    pv_kernel<<<dim3(16, BB * HH), blk, PV_SMEM_BYTES>>>(attn_ptr, vp, ctxp);
    // Wo: K=512 split into 2x256 (256 CTAs), then combine (+bias +resid x)
    sgemm_ksplit_kernel<<<dim3(4, 32, 2), blk, GEMM_SMEM_BYTES>>>(
        ctxp, Wo, partp, DD, DD, 256);
    combine2_kernel<<<NTOK * DD / 4 / 256, blk>>>(partp, bo, x, t1p);
    ln_kernel<<<NTOK, 128>>>(t1p, ln1g, ln1b, aop);
    sgemm_kernel<<<dim3(16, 32), blk, GEMM_SMEM_BYTES>>>(
        aop, W1, b1, nullptr, hp, DFF, DD, 1);
    // FFN2: K=2048 split into 2x1024 (256 CTAs), then combine (+bias +resid aop)
    sgemm_ksplit_kernel<<<dim3(4, 32, 2), blk, GEMM_SMEM_BYTES>>>(
        hp, W2, partp, DD, DFF, 1024);
    combine2_kernel<<<NTOK * DD / 4 / 256, blk>>>(partp, b2, aop, t2p);
    ln_kernel<<<NTOK, 128>>>(t2p, ln2g, ln2b, out);
}